// round 3
// baseline (speedup 1.0000x reference)
#include <cuda_runtime.h>
#include <cstdint>

#define BB 32
#define CC 384
#define TT 512
#define MF 6656  // MAX_FRAMES = 512*13

// Scratch token map: tok[b][p] = source token index, -1 = masked (past frame_lengths)
__device__ int16_t g_tok[BB * MF];

// One block per batch: repeat counts -> inclusive scan -> scatter token map,
// pitch output, and frame_lengths.
__global__ void prep_kernel(const float* __restrict__ duration,
                            const float* __restrict__ notepitch,
                            float* __restrict__ out) {
    const int b = blockIdx.x;
    const int t = threadIdx.x;  // 0..511
    __shared__ int s[TT];

    // repeat count, bit-exact vs jax float32 reference
    const float d  = duration[b * TT + t];
    const float fr = 44100.0f * d;
    float rf;
    if (fr - 1024.0f > 0.0f)
        rf = fmaxf((fr - 1024.0f) * (1.0f / 256.0f), 1.0f);  // /256 exact
    else
        rf = (d == 0.0f) ? 0.0f : 1.0f;
    const int r = (int)rf;  // truncation == astype(int32)

    // inclusive block scan (Hillis-Steele)
    s[t] = r;
    __syncthreads();
    #pragma unroll
    for (int off = 1; off < TT; off <<= 1) {
        int v = (t >= off) ? s[t - off] : 0;
        __syncthreads();
        s[t] += v;
        __syncthreads();
    }
    const int end   = s[t];
    const int start = (t == 0) ? 0 : s[t - 1];
    const int flen  = s[TT - 1];

    float* pitch_out = out + (size_t)BB * CC * MF + (size_t)b * MF;
    int16_t* tokb    = g_tok + b * MF;

    // pitch value: int32 cast then back to float (identity for integer-valued input)
    const float pv = (float)(int)notepitch[b * TT + t];

    // scatter: token t covers frames [start, end)
    for (int p = start; p < end; ++p) {
        tokb[p]      = (int16_t)t;
        pitch_out[p] = pv;
    }
    // masked tail: frames [flen, MF)
    for (int p = flen + t; p < MF; p += TT) {
        tokb[p]      = -1;
        pitch_out[p] = 0.0f;
    }
    if (t == 0) {
        out[(size_t)BB * CC * MF + (size_t)BB * MF + b] = (float)flen;
    }
}

// Expansion: out[b, c, p] = tok>=0 ? x[b, c, tok] : 0
// grid = (MF/512, CC/32, BB), block = 128 threads, 4 frames/thread (float4 stores)
__global__ void expand_kernel(const float* __restrict__ x,
                              float* __restrict__ out) {
    const int b  = blockIdx.z;
    const int c0 = blockIdx.y * 32;
    const int p0 = blockIdx.x * 512 + threadIdx.x * 4;

    const short4 tk4 = *reinterpret_cast<const short4*>(g_tok + b * MF + p0);
    int t0 = tk4.x, t1 = tk4.y, t2 = tk4.z, t3 = tk4.w;
    const bool m0 = t0 >= 0, m1 = t1 >= 0, m2 = t2 >= 0, m3 = t3 >= 0;
    t0 &= (TT - 1); t1 &= (TT - 1); t2 &= (TT - 1); t3 &= (TT - 1);  // -1 -> 511 (valid addr)

    const float* xb = x   + ((size_t)b * CC + c0) * TT;
    float*       ob = out + ((size_t)b * CC + c0) * MF + p0;

    #pragma unroll 4
    for (int c = 0; c < 32; ++c) {
        const float* xr = xb + c * TT;
        float4 v;
        v.x = m0 ? xr[t0] : 0.0f;
        v.y = m1 ? xr[t1] : 0.0f;
        v.z = m2 ? xr[t2] : 0.0f;
        v.w = m3 ? xr[t3] : 0.0f;
        *reinterpret_cast<float4*>(ob + (size_t)c * MF) = v;
    }
}

extern "C" void kernel_launch(void* const* d_in, const int* in_sizes, int n_in,
                              void* d_out, int out_size) {
    const float* x         = (const float*)d_in[0];
    const float* notepitch = (const float*)d_in[1];
    const float* duration  = (const float*)d_in[2];
    // d_in[3] = x_lengths: unused by the reference computation
    float* out = (float*)d_out;

    prep_kernel<<<BB, TT>>>(duration, notepitch, out);
    expand_kernel<<<dim3(MF / 512, CC / 32, BB), 128>>>(x, out);
}